// round 2
// baseline (speedup 1.0000x reference)
#include <cuda_runtime.h>

// FastFood layer, D=1024, R=4, M=16384 rows. One warp per row.
//
// FWHT_1024 = H32 (idx bits 5-9) (x) H32 (idx bits 0-4).
// Two register layouts per warp:
//   A: v[k] @ lane l  <->  idx = k*32 + l   (reg index = high bits)
//   B: v[k] @ lane l  <->  idx = l*32 + k   (reg index = low bits)
// Each FWHT = reg-butterflies + padded-smem transpose + reg-butterflies
// (zero shuffles, all smem accesses bank-conflict-free via stride-33 padding).
// pad(i) = i + (i>>5)  maps true index -> padded smem slot.

#define FF_D 1024
#define FF_R 4
#define WARPS_PER_BLOCK 8
#define THREADS (WARPS_PER_BLOCK * 32)

// B is +/-1: pack sign bits once per launch. g_bpack[r*32 + l] bit k = signbit(B[r][k*32+l]).
__device__ unsigned int g_bpack[FF_R * 32];

__global__ void pack_b_kernel(const float* __restrict__ B) {
    int t = threadIdx.x;                 // 0..127
    int r = t >> 5, l = t & 31;
    unsigned int m = 0;
    #pragma unroll
    for (int k = 0; k < 32; k++)
        m |= (__float_as_uint(B[r * FF_D + k * 32 + l]) >> 31) << k;
    g_bpack[t] = m;
}

__device__ __forceinline__ void fwht_reg(float v[32]) {
    // H32 over the 5 register-index bits (pure FADD, no cross-lane traffic)
    #pragma unroll
    for (int m = 1; m <= 16; m <<= 1) {
        #pragma unroll
        for (int k = 0; k < 32; k++) {
            if ((k & m) == 0) {
                float a = v[k], b = v[k | m];
                v[k]     = a + b;
                v[k | m] = a - b;
            }
        }
    }
}

__global__ __launch_bounds__(THREADS, 3)
void fastfood_kernel(const float* __restrict__ x,
                     const float* __restrict__ G,
                     const float* __restrict__ S,
                     const int*   __restrict__ P,
                     float* __restrict__ out, int M)
{
    __shared__ float sc[WARPS_PER_BLOCK][32 * 33];   // 4224 B per warp, stride-33 padded
    const int warp = threadIdx.x >> 5;
    const int lane = threadIdx.x & 31;
    const int row  = blockIdx.x * WARPS_PER_BLOCK + warp;
    if (row >= M) return;
    float* sm = sc[warp];

    // Load the row once (layout A), keep it across all R transforms.
    float xv[32];
    const float* xr = x + (size_t)row * FF_D;
    #pragma unroll
    for (int k = 0; k < 32; k++) xv[k] = xr[k * 32 + lane];

    #pragma unroll 1
    for (int r = 0; r < FF_R; r++) {
        // ---- v = x * B[r]  (sign-bit xor, no table loads) ----
        const unsigned int bp = g_bpack[r * 32 + lane];
        float v[32];
        #pragma unroll
        for (int k = 0; k < 32; k++)
            v[k] = __uint_as_float(__float_as_uint(xv[k]) ^ ((bp << (31 - k)) & 0x80000000u));

        // ---- FWHT #1 ----
        fwht_reg(v);                                  // bits 5-9 (layout A)
        __syncwarp();
        #pragma unroll
        for (int k = 0; k < 32; k++) sm[k * 33 + lane] = v[k];     // store pad(k*32+l): CF
        __syncwarp();
        #pragma unroll
        for (int k = 0; k < 32; k++) v[k] = sm[lane * 33 + k];     // load pad(l*32+k): CF -> layout B
        fwht_reg(v);                                  // bits 0-4

        // ---- permutation gather + G (stay in layout B) ----
        __syncwarp();
        #pragma unroll
        for (int k = 0; k < 32; k++) sm[lane * 33 + k] = v[k];     // sm[pad(i)] = h1[i], CF
        __syncwarp();
        const int*   Pr = P + r * FF_D + lane * 32;
        const float* Gr = G + r * FF_D + lane * 32;
        #pragma unroll
        for (int q = 0; q < 8; q++) {
            int4   p4 = *reinterpret_cast<const int4*>(Pr + 4 * q);
            float4 g4 = *reinterpret_cast<const float4*>(Gr + 4 * q);
            v[4*q+0] = sm[p4.x + (p4.x >> 5)] * g4.x;
            v[4*q+1] = sm[p4.y + (p4.y >> 5)] * g4.y;
            v[4*q+2] = sm[p4.z + (p4.z >> 5)] * g4.z;
            v[4*q+3] = sm[p4.w + (p4.w >> 5)] * g4.w;
        }

        // ---- FWHT #2 ----
        fwht_reg(v);                                  // bits 0-4 (layout B)
        __syncwarp();
        #pragma unroll
        for (int k = 0; k < 32; k++) sm[lane * 33 + k] = v[k];     // CF
        __syncwarp();
        #pragma unroll
        for (int k = 0; k < 32; k++) v[k] = sm[k * 33 + lane];     // CF -> layout A
        fwht_reg(v);                                  // bits 5-9

        // ---- scale + coalesced store (layout A) ----
        const float* Sr = S + r * FF_D;
        float* o = out + (size_t)row * (FF_R * FF_D) + r * FF_D;
        #pragma unroll
        for (int k = 0; k < 32; k++) {
            int j = k * 32 + lane;
            o[j] = v[k] * (Sr[j] * 0.03125f);         // 1/sqrt(1024)
        }
    }
}

extern "C" void kernel_launch(void* const* d_in, const int* in_sizes, int n_in,
                              void* d_out, int out_size) {
    const float* x = (const float*)d_in[0];   // (4,512,8,1024) fp32
    const float* B = (const float*)d_in[1];   // (4,1024) fp32
    const float* G = (const float*)d_in[2];   // (4,1024) fp32
    const float* S = (const float*)d_in[3];   // (4,1024) fp32
    const int*   P = (const int*)  d_in[4];   // (4,1024) int32
    float* out = (float*)d_out;

    const int M = in_sizes[0] / FF_D;         // 16384 rows
    pack_b_kernel<<<1, FF_R * 32>>>(B);
    const int blocks = (M + WARPS_PER_BLOCK - 1) / WARPS_PER_BLOCK;
    fastfood_kernel<<<blocks, THREADS>>>(x, G, S, P, out, M);
}